// round 1
// baseline (speedup 1.0000x reference)
#include <cuda_runtime.h>

// Two-pass deterministic reduction:
//   pass 1: grid-stride over (x,y,z) triplets, vectorized float4 loads,
//           per-block partial sums into __device__ scratch (no atomics).
//   pass 2: single block reduces partials in double, scales, writes d_out[0].

#define GRID  1184
#define BLOCK 256

__device__ float g_partials[GRID];

__global__ void __launch_bounds__(BLOCK)
dist_sum_kernel(const float4* __restrict__ p, const float4* __restrict__ t,
                long long ngroups)  // each group = 3 float4 = 4 triplets
{
    float acc = 0.0f;
    const long long stride = (long long)gridDim.x * blockDim.x;
    for (long long g = (long long)blockIdx.x * blockDim.x + threadIdx.x;
         g < ngroups; g += stride) {
        const long long base = 3 * g;
        float4 pa = p[base + 0], pb = p[base + 1], pc = p[base + 2];
        float4 ta = t[base + 0], tb = t[base + 1], tc = t[base + 2];

        float d0x = pa.x - ta.x, d0y = pa.y - ta.y, d0z = pa.z - ta.z;
        float d1x = pa.w - ta.w, d1y = pb.x - tb.x, d1z = pb.y - tb.y;
        float d2x = pb.z - tb.z, d2y = pb.w - tb.w, d2z = pc.x - tc.x;
        float d3x = pc.y - tc.y, d3y = pc.z - tc.z, d3z = pc.w - tc.w;

        acc += sqrtf(fmaf(d0x, d0x, fmaf(d0y, d0y, d0z * d0z)));
        acc += sqrtf(fmaf(d1x, d1x, fmaf(d1y, d1y, d1z * d1z)));
        acc += sqrtf(fmaf(d2x, d2x, fmaf(d2y, d2y, d2z * d2z)));
        acc += sqrtf(fmaf(d3x, d3x, fmaf(d3y, d3y, d3z * d3z)));
    }

    // intra-warp reduce
    #pragma unroll
    for (int o = 16; o > 0; o >>= 1)
        acc += __shfl_down_sync(0xffffffffu, acc, o);

    __shared__ float sm[BLOCK / 32];
    if ((threadIdx.x & 31) == 0) sm[threadIdx.x >> 5] = acc;
    __syncthreads();

    if (threadIdx.x < 32) {
        float v = (threadIdx.x < BLOCK / 32) ? sm[threadIdx.x] : 0.0f;
        #pragma unroll
        for (int o = 4; o > 0; o >>= 1)
            v += __shfl_down_sync(0xffffffffu, v, o);
        if (threadIdx.x == 0) g_partials[blockIdx.x] = v;
    }
}

__global__ void __launch_bounds__(1024)
final_reduce_kernel(float* __restrict__ out, double inv_count)
{
    double acc = 0.0;
    for (int i = threadIdx.x; i < GRID; i += blockDim.x)
        acc += (double)g_partials[i];

    #pragma unroll
    for (int o = 16; o > 0; o >>= 1)
        acc += __shfl_down_sync(0xffffffffu, acc, o);

    __shared__ double sm[32];
    if ((threadIdx.x & 31) == 0) sm[threadIdx.x >> 5] = acc;
    __syncthreads();

    if (threadIdx.x < 32) {
        double v = (threadIdx.x < 32) ? sm[threadIdx.x] : 0.0;
        #pragma unroll
        for (int o = 16; o > 0; o >>= 1)
            v += __shfl_down_sync(0xffffffffu, v, o);
        if (threadIdx.x == 0) out[0] = (float)(v * inv_count);
    }
}

extern "C" void kernel_launch(void* const* d_in, const int* in_sizes, int n_in,
                              void* d_out, int out_size)
{
    const float4* pred = (const float4*)d_in[0];
    const float4* targ = (const float4*)d_in[1];
    float* out = (float*)d_out;

    const long long n_elem   = in_sizes[0];        // B * 63 = 66,060,288
    const long long ngroups  = n_elem / 12;        // 4 triplets per group
    const long long n_dists  = n_elem / 3;         // B * 21 distances
    const double    inv_cnt  = 1.0 / (double)n_dists;

    dist_sum_kernel<<<GRID, BLOCK>>>(pred, targ, ngroups);
    final_reduce_kernel<<<1, 1024>>>(out, inv_cnt);
}

// round 2
// speedup vs baseline: 1.0299x; 1.0299x over previous
#include <cuda_runtime.h>

// Single-pass deterministic reduction with "last block finishes":
//   - grid-stride over (x,y,z) triplets, vectorized float4 loads
//   - per-block partial into __device__ scratch (fixed slot per block)
//   - last-arriving block (atomicInc ticket) sums partials in FIXED index
//     order (deterministic), scales, writes d_out, resets the ticket.

#define GRID  1216          // 152 SMs * 8 CTAs
#define BLOCK 256

__device__ float          g_partials[GRID];
__device__ unsigned int   g_ticket = 0;

__global__ void __launch_bounds__(BLOCK)
dist_mean_kernel(const float4* __restrict__ p, const float4* __restrict__ t,
                 long long ngroups,      // each group = 3 float4 = 4 triplets
                 double inv_count,
                 float* __restrict__ out)
{
    float acc = 0.0f;
    const long long stride = (long long)gridDim.x * blockDim.x;
    for (long long g = (long long)blockIdx.x * blockDim.x + threadIdx.x;
         g < ngroups; g += stride) {
        const long long base = 3 * g;
        float4 pa = p[base + 0], pb = p[base + 1], pc = p[base + 2];
        float4 ta = t[base + 0], tb = t[base + 1], tc = t[base + 2];

        float d0x = pa.x - ta.x, d0y = pa.y - ta.y, d0z = pa.z - ta.z;
        float d1x = pa.w - ta.w, d1y = pb.x - tb.x, d1z = pb.y - tb.y;
        float d2x = pb.z - tb.z, d2y = pb.w - tb.w, d2z = pc.x - tc.x;
        float d3x = pc.y - tc.y, d3y = pc.z - tc.z, d3z = pc.w - tc.w;

        acc += sqrtf(fmaf(d0x, d0x, fmaf(d0y, d0y, d0z * d0z)));
        acc += sqrtf(fmaf(d1x, d1x, fmaf(d1y, d1y, d1z * d1z)));
        acc += sqrtf(fmaf(d2x, d2x, fmaf(d2y, d2y, d2z * d2z)));
        acc += sqrtf(fmaf(d3x, d3x, fmaf(d3y, d3y, d3z * d3z)));
    }

    // intra-warp reduce
    #pragma unroll
    for (int o = 16; o > 0; o >>= 1)
        acc += __shfl_down_sync(0xffffffffu, acc, o);

    __shared__ float sm[BLOCK / 32];
    if ((threadIdx.x & 31) == 0) sm[threadIdx.x >> 5] = acc;
    __syncthreads();

    __shared__ bool s_last;
    if (threadIdx.x < 32) {
        float v = (threadIdx.x < BLOCK / 32) ? sm[threadIdx.x] : 0.0f;
        #pragma unroll
        for (int o = 4; o > 0; o >>= 1)
            v += __shfl_down_sync(0xffffffffu, v, o);
        if (threadIdx.x == 0) {
            g_partials[blockIdx.x] = v;
            __threadfence();                          // partial visible before ticket
            unsigned int t = atomicInc(&g_ticket, GRID - 1);
            s_last = (t == GRID - 1);
        }
    }
    __syncthreads();

    if (!s_last) return;

    // ---- last block: deterministic final reduce ----
    // 256 threads, ceil(1216/256)=5 partials each, double accumulation.
    double dacc = 0.0;
    #pragma unroll
    for (int i = threadIdx.x; i < GRID; i += BLOCK)
        dacc += (double)g_partials[i];

    #pragma unroll
    for (int o = 16; o > 0; o >>= 1)
        dacc += __shfl_down_sync(0xffffffffu, dacc, o);

    __shared__ double dsm[BLOCK / 32];
    if ((threadIdx.x & 31) == 0) dsm[threadIdx.x >> 5] = dacc;
    __syncthreads();

    if (threadIdx.x == 0) {
        double v = 0.0;
        #pragma unroll
        for (int i = 0; i < BLOCK / 32; i++) v += dsm[i];
        out[0] = (float)(v * inv_count);
        // g_ticket wrapped to 0 via atomicInc's modulus — ready for next replay
    }
}

extern "C" void kernel_launch(void* const* d_in, const int* in_sizes, int n_in,
                              void* d_out, int out_size)
{
    const float4* pred = (const float4*)d_in[0];
    const float4* targ = (const float4*)d_in[1];
    float* out = (float*)d_out;

    const long long n_elem  = in_sizes[0];        // B * 63 = 66,060,288
    const long long ngroups = n_elem / 12;        // 4 triplets per group
    const long long n_dists = n_elem / 3;         // B * 21 distances
    const double    inv_cnt = 1.0 / (double)n_dists;

    dist_mean_kernel<<<GRID, BLOCK>>>(pred, targ, ngroups, inv_cnt, out);
}

// round 5
// speedup vs baseline: 1.0439x; 1.0136x over previous
#include <cuda_runtime.h>

// Single-pass deterministic reduction with "last block finishes".
// GRID = 152 SMs * 6 CTAs (matches 40-reg residency -> exactly one wave).
// Streaming loads (__ldcs): touch-once data, evict-first from L2.

#define GRID  912           // 152 SMs * 6 resident CTAs @ 40 regs
#define BLOCK 256

__device__ float          g_partials[GRID];
__device__ unsigned int   g_ticket = 0;

__global__ void __launch_bounds__(BLOCK)
dist_mean_kernel(const float4* __restrict__ p, const float4* __restrict__ t,
                 long long ngroups,      // each group = 3 float4 = 4 triplets
                 double inv_count,
                 float* __restrict__ out)
{
    float acc = 0.0f;
    const long long stride = (long long)gridDim.x * blockDim.x;
    for (long long g = (long long)blockIdx.x * blockDim.x + threadIdx.x;
         g < ngroups; g += stride) {
        const long long base = 3 * g;
        float4 pa = __ldcs(&p[base + 0]);
        float4 pb = __ldcs(&p[base + 1]);
        float4 pc = __ldcs(&p[base + 2]);
        float4 ta = __ldcs(&t[base + 0]);
        float4 tb = __ldcs(&t[base + 1]);
        float4 tc = __ldcs(&t[base + 2]);

        float d0x = pa.x - ta.x, d0y = pa.y - ta.y, d0z = pa.z - ta.z;
        float d1x = pa.w - ta.w, d1y = pb.x - tb.x, d1z = pb.y - tb.y;
        float d2x = pb.z - tb.z, d2y = pb.w - tb.w, d2z = pc.x - tc.x;
        float d3x = pc.y - tc.y, d3y = pc.z - tc.z, d3z = pc.w - tc.w;

        acc += sqrtf(fmaf(d0x, d0x, fmaf(d0y, d0y, d0z * d0z)));
        acc += sqrtf(fmaf(d1x, d1x, fmaf(d1y, d1y, d1z * d1z)));
        acc += sqrtf(fmaf(d2x, d2x, fmaf(d2y, d2y, d2z * d2z)));
        acc += sqrtf(fmaf(d3x, d3x, fmaf(d3y, d3y, d3z * d3z)));
    }

    // intra-warp reduce
    #pragma unroll
    for (int o = 16; o > 0; o >>= 1)
        acc += __shfl_down_sync(0xffffffffu, acc, o);

    __shared__ float sm[BLOCK / 32];
    if ((threadIdx.x & 31) == 0) sm[threadIdx.x >> 5] = acc;
    __syncthreads();

    __shared__ bool s_last;
    if (threadIdx.x < 32) {
        float v = (threadIdx.x < BLOCK / 32) ? sm[threadIdx.x] : 0.0f;
        #pragma unroll
        for (int o = 4; o > 0; o >>= 1)
            v += __shfl_down_sync(0xffffffffu, v, o);
        if (threadIdx.x == 0) {
            g_partials[blockIdx.x] = v;
            __threadfence();                          // partial visible before ticket
            unsigned int tk = atomicInc(&g_ticket, GRID - 1);
            s_last = (tk == GRID - 1);
        }
    }
    __syncthreads();

    if (!s_last) return;

    // ---- last block: deterministic final reduce ----
    // 256 threads, ceil(912/256)=4 partials each, double accumulation.
    double dacc = 0.0;
    #pragma unroll
    for (int i = threadIdx.x; i < GRID; i += BLOCK)
        dacc += (double)g_partials[i];

    #pragma unroll
    for (int o = 16; o > 0; o >>= 1)
        dacc += __shfl_down_sync(0xffffffffu, dacc, o);

    __shared__ double dsm[BLOCK / 32];
    if ((threadIdx.x & 31) == 0) dsm[threadIdx.x >> 5] = dacc;
    __syncthreads();

    if (threadIdx.x == 0) {
        double v = 0.0;
        #pragma unroll
        for (int i = 0; i < BLOCK / 32; i++) v += dsm[i];
        out[0] = (float)(v * inv_count);
        // g_ticket wrapped to 0 via atomicInc's modulus — ready for next replay
    }
}

extern "C" void kernel_launch(void* const* d_in, const int* in_sizes, int n_in,
                              void* d_out, int out_size)
{
    const float4* pred = (const float4*)d_in[0];
    const float4* targ = (const float4*)d_in[1];
    float* out = (float*)d_out;

    const long long n_elem  = in_sizes[0];        // B * 63 = 66,060,288
    const long long ngroups = n_elem / 12;        // 4 triplets per group
    const long long n_dists = n_elem / 3;         // B * 21 distances
    const double    inv_cnt = 1.0 / (double)n_dists;

    dist_mean_kernel<<<GRID, BLOCK>>>(pred, targ, ngroups, inv_cnt, out);
}